// round 5
// baseline (speedup 1.0000x reference)
#include <cuda_runtime.h>
#include <cstdint>
#include <cstddef>

// Problem constants
#define cT 64
#define cN 8192
#define cF 256
#define cH 256
#define cK 512          // concat K = F + H
#define ROWSC 56        // batch rows per CTA (8 warps x 7 rows)
#define RPW 7           // rows per warp
#define NTHR 256
#define GRID ((cN + ROWSC - 1) / ROWSC)   // 147 CTAs ~= 148 SMs, one wave
#define KTILE 32
#define NCHUNK 16       // cK / KTILE
#define SMEM_BYTES ((ROWSC * cK + 2 * KTILE * cH) * 4)

// Prepped weights: Wt[k][j] = (k<256 ? W_ih[j][k] : W_hh[j][k-256]); combined bias.
__device__ float g_Wt[cK * cH];
__device__ float g_b[cH];

__global__ void prep_kernel(const float* __restrict__ W_ih, const float* __restrict__ W_hh,
                            const float* __restrict__ b_ih, const float* __restrict__ b_hh) {
    int idx = blockIdx.x * blockDim.x + threadIdx.x;
    if (idx < cK * cH) {
        int k = idx >> 8;
        int j = idx & 255;
        g_Wt[idx] = (k < cH) ? W_ih[j * cF + k] : W_hh[j * cH + (k - cH)];
    }
    if (idx < cH) g_b[idx] = b_ih[idx] + b_hh[idx];
}

// ---- packed f32x2 helpers (sm_103a) ----
__device__ __forceinline__ unsigned long long pk2(float lo, float hi) {
    unsigned long long r;
    asm("mov.b64 %0, {%1, %2};" : "=l"(r) : "f"(lo), "f"(hi));
    return r;
}
__device__ __forceinline__ void upk2(unsigned long long v, float& lo, float& hi) {
    asm("mov.b64 {%0, %1}, %2;" : "=f"(lo), "=f"(hi) : "l"(v));
}
__device__ __forceinline__ unsigned long long ffma2(unsigned long long a,
                                                    unsigned long long b,
                                                    unsigned long long c) {
    unsigned long long d;
    asm("fma.rn.f32x2 %0, %1, %2, %3;" : "=l"(d) : "l"(a), "l"(b), "l"(c));
    return d;
}

__device__ __forceinline__ void cp16(uint32_t saddr, const void* g) {
    asm volatile("cp.async.cg.shared.global [%0], [%1], 16;" :: "r"(saddr), "l"(g));
}

__global__ __launch_bounds__(NTHR, 1)
void rnn_kernel(const float* __restrict__ X, const float* __restrict__ ln_w,
                const float* __restrict__ ln_b, float* __restrict__ out) {
    extern __shared__ float smem[];
    float* A  = smem;                 // [ROWSC][cK] : cols 0..255 = x_t, 256..511 = h
    float* Ws = smem + ROWSC * cK;    // [2][KTILE][cH]

    const int tid  = threadIdx.x;
    const int lane = tid & 31;
    const int warp = tid >> 5;        // 8 warps, RPW rows each
    const int n0   = blockIdx.x * ROWSC;

    const uint32_t ws_smem = (uint32_t)__cvta_generic_to_shared(Ws);
    const uint32_t a_smem  = (uint32_t)__cvta_generic_to_shared(A);

    // Per-thread constants: bias / layernorm params for cols {2*lane + 64p, +1}
    unsigned long long binit[4];
    float lw[8], lb[8];
#pragma unroll
    for (int p = 0; p < 4; ++p) {
        int j = 2 * lane + 64 * p;
        float2 b2 = *reinterpret_cast<const float2*>(&g_b[j]);
        binit[p] = pk2(b2.x, b2.y);
        float2 w2 = *reinterpret_cast<const float2*>(&ln_w[j]);
        float2 z2 = *reinterpret_cast<const float2*>(&ln_b[j]);
        lw[2 * p] = w2.x; lw[2 * p + 1] = w2.y;
        lb[2 * p] = z2.x; lb[2 * p + 1] = z2.y;
    }

    // Zero the h region of A (cols 256..511): ROWSC*cH/4 = 3584 float4, 14/thread
    {
        float4 z = make_float4(0.f, 0.f, 0.f, 0.f);
#pragma unroll
        for (int q = 0; q < 14; ++q) {
            int flat = (tid + NTHR * q) * 4;        // 0..14335 floats
            int r = flat >> 8;
            int c = flat & 255;
            *reinterpret_cast<float4*>(&A[r * cK + cH + c]) = z;
        }
    }

    // W-chunk cp.async issue: one KTILE x 256 tile (32 KB), 8x16B per thread
    auto issue_w = [&](int ch, int buf) {
        const float4* src = reinterpret_cast<const float4*>(g_Wt) + ch * (KTILE * cH / 4) + tid;
        uint32_t dst = ws_smem + buf * (KTILE * cH * 4) + tid * 16;
#pragma unroll
        for (int q = 0; q < 8; ++q) cp16(dst + q * 4096, src + q * 256);
        asm volatile("cp.async.commit_group;" ::: "memory");
    };

    for (int it = 0; it <= cT; ++it) {
        // Load x_t tile into A cols 0..255 via cp.async (it==0 pre-step and it==1
        // both use t=0). These commit in the same group as W-chunk 0, so the
        // first wait_group(0)+__syncthreads below orders them before any GEMM read.
        // Tail CTA: clamp global row (duplicate data; those rows are never stored).
        const int t = (it == 0) ? 0 : (it - 1);
        const float* xbase = X + (size_t)t * cN * cF;
#pragma unroll
        for (int q = 0; q < 14; ++q) {
            int f4 = tid + NTHR * q;                // float4 index, 0..3583
            int flat = f4 * 4;
            int r = flat >> 8;
            int c = flat & 255;
            int gr = n0 + r; if (gr > cN - 1) gr = cN - 1;
            cp16(a_smem + (uint32_t)(r * cK + c) * 4,
                 xbase + (size_t)gr * cF + c);
        }

        // Accumulators = bias
        unsigned long long acc[RPW][4];
#pragma unroll
        for (int rr = 0; rr < RPW; ++rr)
#pragma unroll
            for (int p = 0; p < 4; ++p) acc[rr][p] = binit[p];

        issue_w(0, 0);   // commits x-tile + W chunk 0 together

        for (int ch = 0; ch < NCHUNK; ++ch) {
            asm volatile("cp.async.wait_group 0;" ::: "memory");
            __syncthreads();     // W tile (and x tile on ch==0) ready; h STS visible
            if (ch + 1 < NCHUNK) issue_w(ch + 1, (ch + 1) & 1);

            const char* wb = reinterpret_cast<const char*>(Ws) + (ch & 1) * (KTILE * cH * 4);
            const int k0 = ch * KTILE;
#pragma unroll
            for (int kb = 0; kb < KTILE; kb += 2) {
                unsigned long long w0[4], w1[4];
#pragma unroll
                for (int p = 0; p < 4; ++p) {
                    int off = 8 * lane + 256 * p;
                    w0[p] = *reinterpret_cast<const unsigned long long*>(wb + kb * 1024 + off);
                    w1[p] = *reinterpret_cast<const unsigned long long*>(wb + (kb + 1) * 1024 + off);
                }
#pragma unroll
                for (int rr = 0; rr < RPW; ++rr) {
                    float2 a2 = *reinterpret_cast<const float2*>(
                        &A[(warp * RPW + rr) * cK + k0 + kb]);   // same addr all lanes: broadcast
                    unsigned long long d0 = pk2(a2.x, a2.x);
                    unsigned long long d1 = pk2(a2.y, a2.y);
#pragma unroll
                    for (int p = 0; p < 4; ++p) acc[rr][p] = ffma2(d0, w0[p], acc[rr][p]);
#pragma unroll
                    for (int p = 0; p < 4; ++p) acc[rr][p] = ffma2(d1, w1[p], acc[rr][p]);
                }
            }
        }
        __syncthreads();  // all warps done reading A before h writeback / next x load

        // Epilogue: relu (it>0), h writeback, LayerNorm + guarded store (it>0)
#pragma unroll
        for (int rr = 0; rr < RPW; ++rr) {
            const int row = warp * RPW + rr;
            float v[8];
#pragma unroll
            for (int p = 0; p < 4; ++p) upk2(acc[rr][p], v[2 * p], v[2 * p + 1]);
            if (it > 0) {
#pragma unroll
                for (int i = 0; i < 8; ++i) v[i] = fmaxf(v[i], 0.f);
            }
            // h writeback into A cols 256..511 (warp-private rows)
#pragma unroll
            for (int p = 0; p < 4; ++p) {
                *reinterpret_cast<float2*>(&A[row * cK + cH + 2 * lane + 64 * p]) =
                    make_float2(v[2 * p], v[2 * p + 1]);
            }
            if (it > 0 && n0 + row < cN) {
                float s = 0.f, s2 = 0.f;
#pragma unroll
                for (int i = 0; i < 8; ++i) { s += v[i]; s2 += v[i] * v[i]; }
#pragma unroll
                for (int off = 16; off >= 1; off >>= 1) {
                    s  += __shfl_xor_sync(0xffffffffu, s,  off);
                    s2 += __shfl_xor_sync(0xffffffffu, s2, off);
                }
                const float mean = s * (1.f / 256.f);
                const float var  = s2 * (1.f / 256.f) - mean * mean;
                const float rstd = rsqrtf(var + 1e-5f);
                float* orow = out + (((size_t)(it - 1) * cN) + n0 + row) * cH;
#pragma unroll
                for (int p = 0; p < 4; ++p) {
                    float2 y;
                    y.x = (v[2 * p]     - mean) * rstd * lw[2 * p]     + lb[2 * p];
                    y.y = (v[2 * p + 1] - mean) * rstd * lw[2 * p + 1] + lb[2 * p + 1];
                    *reinterpret_cast<float2*>(&orow[2 * lane + 64 * p]) = y;
                }
            }
        }
        // No sync needed here: next iteration's first wait_group+__syncthreads orders
        // the h/x SMEM stores before any GEMM read.
    }
}

extern "C" void kernel_launch(void* const* d_in, const int* in_sizes, int n_in,
                              void* d_out, int out_size) {
    const float* X    = (const float*)d_in[0];
    const float* W_ih = (const float*)d_in[1];
    const float* W_hh = (const float*)d_in[2];
    const float* b_ih = (const float*)d_in[3];
    const float* b_hh = (const float*)d_in[4];
    const float* ln_w = (const float*)d_in[5];
    const float* ln_b = (const float*)d_in[6];
    float* out = (float*)d_out;

    prep_kernel<<<(cK * cH + 255) / 256, 256>>>(W_ih, W_hh, b_ih, b_hh);

    cudaFuncSetAttribute(rnn_kernel, cudaFuncAttributeMaxDynamicSharedMemorySize, SMEM_BYTES);
    rnn_kernel<<<GRID, NTHR, SMEM_BYTES>>>(X, ln_w, ln_b, out);
}